// round 1
// baseline (speedup 1.0000x reference)
#include <cuda_runtime.h>
#include <math.h>

#define BATCH 2
#define SEQ   2048
#define DM    512
#define NH    8
#define HD    64
#define ROWS  (BATCH*SEQ)      // 4096
#define SCALE 0.125f           // 1/sqrt(64)
#define EPS   1e-5f

// ---------------- scratch (static device memory; no allocs allowed) -------------
__device__ float g_xn  [ROWS*DM];
__device__ float g_q   [ROWS*DM];
__device__ float g_k   [ROWS*DM];
__device__ float g_v   [ROWS*DM];
__device__ float g_t1  [ROWS*DM];
__device__ float g_attn[ROWS*DM];
__device__ float g_proj[ROWS*DM];
__device__ float g_s   [4L*SEQ*SEQ];   // scores for the 2 global heads x 2 batches
__device__ float g_tl  [ROWS];

// ---------------- reductions ----------------
__device__ __forceinline__ float warp_red_sum(float v){
#pragma unroll
    for (int o=16;o;o>>=1) v += __shfl_xor_sync(0xffffffffu, v, o);
    return v;
}
__device__ __forceinline__ float warp_red_max(float v){
#pragma unroll
    for (int o=16;o;o>>=1) v = fmaxf(v, __shfl_xor_sync(0xffffffffu, v, o));
    return v;
}
__device__ float block_red_sum(float v, float* sh){
    __syncthreads();
    int lane = threadIdx.x & 31, wid = threadIdx.x >> 5;
    v = warp_red_sum(v);
    if (lane==0) sh[wid] = v;
    __syncthreads();
    int nw = (blockDim.x + 31) >> 5;
    float r = (threadIdx.x < nw) ? sh[threadIdx.x] : 0.f;
    r = warp_red_sum(r);
    if (threadIdx.x==0) sh[0] = r;
    __syncthreads();
    return sh[0];
}
__device__ float block_red_max(float v, float* sh){
    __syncthreads();
    int lane = threadIdx.x & 31, wid = threadIdx.x >> 5;
    v = warp_red_max(v);
    if (lane==0) sh[wid] = v;
    __syncthreads();
    int nw = (blockDim.x + 31) >> 5;
    float r = (threadIdx.x < nw) ? sh[threadIdx.x] : -1e30f;
    r = warp_red_max(r);
    if (threadIdx.x==0) sh[0] = r;
    __syncthreads();
    return sh[0];
}

// ---------------- layernorm (input) ----------------
__global__ void ln_kernel(const float* __restrict__ x, const float* __restrict__ g,
                          const float* __restrict__ b, float* __restrict__ out){
    __shared__ float sh[33];
    int row = blockIdx.x;
    const float* xr = x + (long)row*DM;
    float s=0.f, s2=0.f;
    for (int d=threadIdx.x; d<DM; d+=blockDim.x){ float v=xr[d]; s+=v; s2+=v*v; }
    s  = block_red_sum(s,  sh);
    s2 = block_red_sum(s2, sh);
    float mu  = s * (1.0f/DM);
    float var = s2 * (1.0f/DM) - mu*mu;
    float inv = rsqrtf(var + EPS);
    float* o = out + (long)row*DM;
    for (int d=threadIdx.x; d<DM; d+=blockDim.x)
        o[d] = (xr[d]-mu)*inv*g[d] + b[d];
}

// ---------------- tiled SGEMM  C = A @ op(B)  ----------------
// A[M,K] row-major (lda). TRANSB=1: C[m,n]=sum_k A[m,k]*B[n,k] (ldb over n-rows).
// TRANSB=0: C[m,n]=sum_k A[m,k]*B[k,n]. MODE==1: C = tanh(acc + bias[n]).
// batched via blockIdx.z: z -> (zh=z>>1, zl=z&1) offsets.
#define GBM 64
#define GBN 64
#define GBK 16
template<int MODE, int TRANSB>
__global__ void gemm_kernel(const float* __restrict__ A, const float* __restrict__ B,
                            const float* __restrict__ bias, float* __restrict__ C,
                            int M, int N, int K, int lda, int ldb, int ldc,
                            long offA_hi, long offA_lo, long offB_hi, long offB_lo,
                            long offC_hi, long offC_lo)
{
    int z = blockIdx.z, zh = z >> 1, zl = z & 1;
    A += zh*offA_hi + zl*offA_lo;
    B += zh*offB_hi + zl*offB_lo;
    C += zh*offC_hi + zl*offC_lo;

    __shared__ __align__(16) float As[GBM][GBK+1];
    __shared__ __align__(16) float Bs[GBK][GBN+4];

    int tid = threadIdx.x;
    int tx = tid & 15, ty = tid >> 4;
    int m0 = blockIdx.y*GBM, n0 = blockIdx.x*GBN;

    float acc[4][4] = {};

    for (int k0=0; k0<K; k0+=GBK){
#pragma unroll
        for (int i=0;i<4;i++){
            int idx = tid + i*256;
            int m = idx >> 4, kk = idx & 15;
            As[m][kk] = A[(long)(m0+m)*lda + (k0+kk)];
        }
        if (TRANSB){
#pragma unroll
            for (int i=0;i<4;i++){
                int idx = tid + i*256;
                int n = idx >> 4, kk = idx & 15;
                Bs[kk][n] = B[(long)(n0+n)*ldb + (k0+kk)];
            }
        } else {
#pragma unroll
            for (int i=0;i<4;i++){
                int idx = tid + i*256;
                int kk = idx >> 6, n = idx & 63;
                Bs[kk][n] = B[(long)(k0+kk)*ldb + (n0+n)];
            }
        }
        __syncthreads();
#pragma unroll
        for (int kk=0; kk<GBK; kk++){
            float a0 = As[ty*4+0][kk];
            float a1 = As[ty*4+1][kk];
            float a2 = As[ty*4+2][kk];
            float a3 = As[ty*4+3][kk];
            float4 b4 = *(const float4*)&Bs[kk][tx*4];
            acc[0][0]+=a0*b4.x; acc[0][1]+=a0*b4.y; acc[0][2]+=a0*b4.z; acc[0][3]+=a0*b4.w;
            acc[1][0]+=a1*b4.x; acc[1][1]+=a1*b4.y; acc[1][2]+=a1*b4.z; acc[1][3]+=a1*b4.w;
            acc[2][0]+=a2*b4.x; acc[2][1]+=a2*b4.y; acc[2][2]+=a2*b4.z; acc[2][3]+=a2*b4.w;
            acc[3][0]+=a3*b4.x; acc[3][1]+=a3*b4.y; acc[3][2]+=a3*b4.z; acc[3][3]+=a3*b4.w;
        }
        __syncthreads();
    }
#pragma unroll
    for (int i=0;i<4;i++){
        int m = m0 + ty*4 + i;
#pragma unroll
        for (int j=0;j<4;j++){
            int n = n0 + tx*4 + j;
            float v = acc[i][j];
            if (MODE==1) v = tanhf(v + bias[n]);
            C[(long)m*ldc + n] = v;
        }
    }
}

// ---------------- dense row softmax for global-head scores (scale fused) ------
__global__ void softmax_s(float* __restrict__ S){
    __shared__ float sh[33];
    float* row = S + (long)blockIdx.y*SEQ*SEQ + (long)blockIdx.x*SEQ;
    float m = -1e30f;
    for (int d=threadIdx.x; d<SEQ; d+=blockDim.x) m = fmaxf(m, row[d]);
    m = block_red_max(m, sh);
    float sum = 0.f;
    for (int d=threadIdx.x; d<SEQ; d+=blockDim.x){
        float e = __expf((row[d]-m)*SCALE);
        row[d] = e; sum += e;
    }
    sum = block_red_sum(sum, sh);
    float inv = 1.0f/sum;
    for (int d=threadIdx.x; d<SEQ; d+=blockDim.x) row[d] *= inv;
}

// ---------------- sparse heads (window / dilated): one warp per query ----------
__global__ void sparse_attn(const float* __restrict__ Q, const float* __restrict__ Kk,
                            const float* __restrict__ V, float* __restrict__ O){
    int hy = blockIdx.y;            // 0..5 -> heads 2..7
    int h  = hy + 2;
    int b  = blockIdx.z;
    int wid = threadIdx.x >> 5, lane = threadIdx.x & 31;
    int q = blockIdx.x*4 + wid;

    int w   = (hy==1) ? 128 : (hy==2) ? 256 : 64;
    int dil = (hy<3)  ? 1   : (1 << (hy-2));

    __shared__ float qs[4][64];
    __shared__ float pbuf[4][520];

    const float* qrow = Q + ((long)(b*SEQ + q)*DM + h*HD);
    qs[wid][lane]    = qrow[lane];
    qs[wid][lane+32] = qrow[lane+32];
    __syncwarp();

    int jlo = -min(w, q/dil);
    int jhi =  min(w, (SEQ-1-q)/dil);
    int cnt = jhi - jlo + 1;

    const float* Kbase = Kk + ((long)b*SEQ*DM + h*HD);
    const float* Vbase = V  + ((long)b*SEQ*DM + h*HD);

    float mmax = -1e30f;
    for (int jj=lane; jj<cnt; jj+=32){
        int k = q + (jlo+jj)*dil;
        const float* kr = Kbase + (long)k*DM;
        float s = 0.f;
#pragma unroll
        for (int d=0; d<HD; d+=4){
            float4 kv = *(const float4*)(kr+d);
            s += qs[wid][d]*kv.x + qs[wid][d+1]*kv.y + qs[wid][d+2]*kv.z + qs[wid][d+3]*kv.w;
        }
        s *= SCALE;
        pbuf[wid][jj] = s;
        mmax = fmaxf(mmax, s);
    }
    mmax = warp_red_max(mmax);
    float sum = 0.f;
    for (int jj=lane; jj<cnt; jj+=32){
        float e = __expf(pbuf[wid][jj] - mmax);
        pbuf[wid][jj] = e;
        sum += e;
    }
    sum = warp_red_sum(sum);
    float inv = 1.0f/sum;
    __syncwarp();

    float o0=0.f, o1=0.f;
    for (int jj=0; jj<cnt; jj++){
        int k = q + (jlo+jj)*dil;
        float p = pbuf[wid][jj];
        const float* vr = Vbase + (long)k*DM;
        o0 += p*vr[lane];
        o1 += p*vr[lane+32];
    }
    float* orow = O + ((long)(b*SEQ + q)*DM + h*HD);
    orow[lane]    = o0*inv;
    orow[lane+32] = o1*inv;
}

// ---------------- T gate: logits = tanh1 . w2 + b2 ----------------
__global__ void tdot_kernel(const float* __restrict__ t1, const float* __restrict__ w2,
                            const float* __restrict__ b2, float* __restrict__ tl){
    __shared__ float sh[33];
    int row = blockIdx.x;
    const float* tr = t1 + (long)row*DM;
    float s = 0.f;
    for (int d=threadIdx.x; d<DM; d+=blockDim.x) s += tr[d]*w2[d];
    s = block_red_sum(s, sh);
    if (threadIdx.x==0) tl[row] = s + b2[0];
}

// softmax over sequence dim per batch (2048 elements, 1024 threads)
__global__ void tsoftmax_kernel(float* __restrict__ tl){
    __shared__ float sh[33];
    float* p = tl + (long)blockIdx.x*SEQ;
    int tid = threadIdx.x;
    float v0 = p[tid], v1 = p[tid+1024];
    float m = block_red_max(fmaxf(v0,v1), sh);
    float e0 = __expf(v0-m), e1 = __expf(v1-m);
    float s = block_red_sum(e0+e1, sh);
    float inv = 1.0f/s;
    p[tid] = e0*inv; p[tid+1024] = e1*inv;
}

// ---------------- final: gate, residual, output layernorm ----------------
__global__ void final_kernel(const float* __restrict__ proj, const float* __restrict__ x0,
                             const float* __restrict__ tl, const float* __restrict__ g,
                             const float* __restrict__ b, float* __restrict__ out){
    __shared__ float sh[33];
    int row = blockIdx.x;
    float t = tl[row];
    const float* pr = proj + (long)row*DM;
    const float* xr = x0   + (long)row*DM;
    float s=0.f, s2=0.f;
    for (int d=threadIdx.x; d<DM; d+=blockDim.x){
        float v = pr[d]*t + xr[d];
        s += v; s2 += v*v;
    }
    s  = block_red_sum(s,  sh);
    s2 = block_red_sum(s2, sh);
    float mu  = s * (1.0f/DM);
    float var = s2 * (1.0f/DM) - mu*mu;
    float inv = rsqrtf(var + EPS);
    float* o = out + (long)row*DM;
    for (int d=threadIdx.x; d<DM; d+=blockDim.x){
        float v = pr[d]*t + xr[d];
        o[d] = (v-mu)*inv*g[d] + b[d];
    }
}

// ---------------- launcher ----------------
extern "C" void kernel_launch(void* const* d_in, const int* in_sizes, int n_in,
                              void* d_out, int out_size)
{
    const float* x      = (const float*)d_in[0];
    const float* Wq     = (const float*)d_in[1];
    const float* Wk     = (const float*)d_in[2];
    const float* Wv     = (const float*)d_in[3];
    const float* Wo     = (const float*)d_in[4];
    const float* T_w1   = (const float*)d_in[5];
    const float* T_b1   = (const float*)d_in[6];
    const float* T_w2   = (const float*)d_in[7];
    const float* T_b2   = (const float*)d_in[8];
    const float* ln_in_g  = (const float*)d_in[9];
    const float* ln_in_b  = (const float*)d_in[10];
    const float* ln_out_g = (const float*)d_in[11];
    const float* ln_out_b = (const float*)d_in[12];
    float* out = (float*)d_out;

    float *xn, *q, *k, *v, *t1, *attn, *proj, *s, *tl;
    cudaGetSymbolAddress((void**)&xn,   g_xn);
    cudaGetSymbolAddress((void**)&q,    g_q);
    cudaGetSymbolAddress((void**)&k,    g_k);
    cudaGetSymbolAddress((void**)&v,    g_v);
    cudaGetSymbolAddress((void**)&t1,   g_t1);
    cudaGetSymbolAddress((void**)&attn, g_attn);
    cudaGetSymbolAddress((void**)&proj, g_proj);
    cudaGetSymbolAddress((void**)&s,    g_s);
    cudaGetSymbolAddress((void**)&tl,   g_tl);

    // 1. input layernorm
    ln_kernel<<<ROWS,128>>>(x, ln_in_g, ln_in_b, xn);

    // 2. projections: Q, K, V, tanh-MLP hidden
    dim3 gproj(DM/GBN, ROWS/GBM, 1);
    gemm_kernel<0,1><<<gproj,256>>>(xn, Wq, nullptr, q,  ROWS, DM, DM, DM, DM, DM, 0,0,0,0,0,0);
    gemm_kernel<0,1><<<gproj,256>>>(xn, Wk, nullptr, k,  ROWS, DM, DM, DM, DM, DM, 0,0,0,0,0,0);
    gemm_kernel<0,1><<<gproj,256>>>(xn, Wv, nullptr, v,  ROWS, DM, DM, DM, DM, DM, 0,0,0,0,0,0);
    gemm_kernel<1,1><<<gproj,256>>>(xn, T_w1, T_b1,  t1, ROWS, DM, DM, DM, DM, DM, 0,0,0,0,0,0);

    // 3. T gate logits + softmax over sequence
    tdot_kernel<<<ROWS,128>>>(t1, T_w2, T_b2, tl);
    tsoftmax_kernel<<<BATCH,1024>>>(tl);

    // 4. global heads (h=0,1): S = Q Kt (batched z=4: zh=batch, zl=head)
    {
        long oAh = (long)SEQ*DM, oAl = HD;            // batch stride / head stride
        long oCh = 2L*SEQ*SEQ,   oCl = (long)SEQ*SEQ;
        dim3 gs(SEQ/GBN, SEQ/GBM, 4);
        gemm_kernel<0,1><<<gs,256>>>(q, k, nullptr, s, SEQ, SEQ, HD, DM, DM, SEQ,
                                     oAh, oAl, oAh, oAl, oCh, oCl);
        softmax_s<<<dim3(SEQ,4),256>>>(s);
        dim3 gav(HD/GBN, SEQ/GBM, 4);
        gemm_kernel<0,0><<<gav,256>>>(s, v, nullptr, attn, SEQ, HD, SEQ, SEQ, DM, DM,
                                      oCh, oCl, oAh, oAl, oAh, oAl);
    }

    // 5. sparse heads (h=2..7)
    sparse_attn<<<dim3(SEQ/4,6,BATCH),128>>>(q, k, v, attn);

    // 6. output projection
    gemm_kernel<0,1><<<gproj,256>>>(attn, Wo, nullptr, proj, ROWS, DM, DM, DM, DM, DM, 0,0,0,0,0,0);

    // 7. gate * out + residual, output layernorm
    final_kernel<<<ROWS,128>>>(proj, x, tl, ln_out_g, ln_out_b, out);
}

// round 3
// speedup vs baseline: 1.5669x; 1.5669x over previous
#include <cuda_runtime.h>
#include <cuda_bf16.h>
#include <math.h>
#include <stdint.h>

#define BATCH 2
#define SEQ   2048
#define DM    512
#define NH    8
#define HD    64
#define ROWS  (BATCH*SEQ)
#define SCALE 0.125f
#define EPS   1e-5f

// ---------------- scratch ----------------
__device__ float g_q   [ROWS*DM];
__device__ float g_k   [ROWS*DM];
__device__ float g_v   [ROWS*DM];
__device__ float g_t1  [ROWS*DM];
__device__ float g_attn[ROWS*DM];
__device__ float g_proj[ROWS*DM];
__device__ float g_s   [4L*SEQ*SEQ];
__device__ float g_tl  [ROWS];

__device__ __nv_bfloat16 g_xnh[ROWS*DM], g_xnl[ROWS*DM];
__device__ __nv_bfloat16 g_qh [ROWS*DM], g_ql [ROWS*DM];
__device__ __nv_bfloat16 g_kh [ROWS*DM], g_kl [ROWS*DM];
__device__ __nv_bfloat16 g_ah [ROWS*DM], g_al [ROWS*DM];
__device__ __nv_bfloat16 g_wqh[DM*DM], g_wql[DM*DM];
__device__ __nv_bfloat16 g_wkh[DM*DM], g_wkl[DM*DM];
__device__ __nv_bfloat16 g_wvh[DM*DM], g_wvl[DM*DM];
__device__ __nv_bfloat16 g_woh[DM*DM], g_wol[DM*DM];
__device__ __nv_bfloat16 g_w1h[DM*DM], g_w1l[DM*DM];
__device__ __nv_bfloat16 g_ph [4L*SEQ*SEQ], g_pl[4L*SEQ*SEQ];
__device__ __nv_bfloat16 g_vth[4L*HD*SEQ],  g_vtl[4L*HD*SEQ];

// ---------------- reductions ----------------
__device__ __forceinline__ float warp_red_sum(float v){
#pragma unroll
    for (int o=16;o;o>>=1) v += __shfl_xor_sync(0xffffffffu, v, o);
    return v;
}
__device__ __forceinline__ float warp_red_max(float v){
#pragma unroll
    for (int o=16;o;o>>=1) v = fmaxf(v, __shfl_xor_sync(0xffffffffu, v, o));
    return v;
}
__device__ float block_red_sum(float v, float* sh){
    __syncthreads();
    int lane = threadIdx.x & 31, wid = threadIdx.x >> 5;
    v = warp_red_sum(v);
    if (lane==0) sh[wid] = v;
    __syncthreads();
    int nw = (blockDim.x + 31) >> 5;
    float r = (threadIdx.x < nw) ? sh[threadIdx.x] : 0.f;
    r = warp_red_sum(r);
    if (threadIdx.x==0) sh[0] = r;
    __syncthreads();
    return sh[0];
}
__device__ float block_red_max(float v, float* sh){
    __syncthreads();
    int lane = threadIdx.x & 31, wid = threadIdx.x >> 5;
    v = warp_red_max(v);
    if (lane==0) sh[wid] = v;
    __syncthreads();
    int nw = (blockDim.x + 31) >> 5;
    float r = (threadIdx.x < nw) ? sh[threadIdx.x] : -1e30f;
    r = warp_red_max(r);
    if (threadIdx.x==0) sh[0] = r;
    __syncthreads();
    return sh[0];
}

__device__ __forceinline__ void split_write(float v, __nv_bfloat16* hi, __nv_bfloat16* lo, long idx){
    __nv_bfloat16 h = __float2bfloat16(v);
    hi[idx] = h;
    lo[idx] = __float2bfloat16(v - __bfloat162float(h));
}

// ---------------- layernorm + split ----------------
__global__ void ln_split(const float* __restrict__ x, const float* __restrict__ g,
                         const float* __restrict__ b,
                         __nv_bfloat16* __restrict__ oh, __nv_bfloat16* __restrict__ ol){
    __shared__ float sh[33];
    int row = blockIdx.x;
    const float* xr = x + (long)row*DM;
    float s=0.f, s2=0.f;
    for (int d=threadIdx.x; d<DM; d+=blockDim.x){ float v=xr[d]; s+=v; s2+=v*v; }
    s  = block_red_sum(s,  sh);
    s2 = block_red_sum(s2, sh);
    float mu  = s * (1.0f/DM);
    float var = s2 * (1.0f/DM) - mu*mu;
    float inv = rsqrtf(var + EPS);
    for (int d=threadIdx.x; d<DM; d+=blockDim.x){
        float v = (xr[d]-mu)*inv*g[d] + b[d];
        split_write(v, oh, ol, (long)row*DM + d);
    }
}

// ---------------- fp32 -> bf16 hi/lo ----------------
__global__ void split2(const float* __restrict__ in, __nv_bfloat16* __restrict__ hi,
                       __nv_bfloat16* __restrict__ lo, long n){
    for (long i = blockIdx.x*(long)blockDim.x + threadIdx.x; i < n; i += (long)gridDim.x*blockDim.x)
        split_write(in[i], hi, lo, i);
}

// ---------------- HMMA mma.sync bf16 hi/lo-split GEMM ----------------
// C[M,N] = A[M,K] @ B[N,K]^T   via Ah*Bh + Ah*Bl + Al*Bh.
// EPI: 0=fp32 C.  1=fp32 C + bf16 hi/lo.  2=tanh(C+bias) fp32.
#define MMA_BF16(d, a, b) \
    asm volatile("mma.sync.aligned.m16n8k16.row.col.f32.bf16.bf16.f32 " \
        "{%0,%1,%2,%3},{%4,%5,%6,%7},{%8,%9},{%0,%1,%2,%3};" \
        : "+f"((d)[0]), "+f"((d)[1]), "+f"((d)[2]), "+f"((d)[3]) \
        : "r"((a)[0]), "r"((a)[1]), "r"((a)[2]), "r"((a)[3]), "r"((b)[0]), "r"((b)[1]))

template<int BM, int BN, int WM, int WN, int EPI>
__global__ void __launch_bounds__(256) hmma_gemm(
    const __nv_bfloat16* __restrict__ Ah, const __nv_bfloat16* __restrict__ Al,
    const __nv_bfloat16* __restrict__ Bh, const __nv_bfloat16* __restrict__ Bl,
    float* __restrict__ C, __nv_bfloat16* __restrict__ Ch, __nv_bfloat16* __restrict__ Cl,
    const float* __restrict__ bias,
    int K, int lda, int ldb, int ldc,
    long oAh, long oAl, long oBh, long oBl, long oCh, long oCl)
{
    constexpr int WTM = BM / WM;        // 32
    constexpr int WTN = BN / WN;
    constexpr int MF  = WTM / 16;       // 2
    constexpr int NF  = WTN / 8;
    constexpr int KS  = 40;             // smem row stride (elements): conflict-free

    __shared__ __nv_bfloat16 sAh[BM*KS], sAl[BM*KS], sBh[BN*KS], sBl[BN*KS];

    const int tid = threadIdx.x;
    const int wid = tid >> 5, lane = tid & 31;
    const int wm = wid % WM, wn = wid / WM;
    const int g = lane >> 2, tg = lane & 3;

    const int z = blockIdx.z, zh = z >> 1, zl = z & 1;
    Ah += zh*oAh + zl*oAl;  Al += zh*oAh + zl*oAl;
    Bh += zh*oBh + zl*oBl;  Bl += zh*oBh + zl*oBl;
    const long co = zh*oCh + zl*oCl;

    const int m0 = blockIdx.y*BM, n0 = blockIdx.x*BN;

    float acc[MF][NF][4];
#pragma unroll
    for (int i=0;i<MF;i++)
#pragma unroll
        for (int j=0;j<NF;j++)
#pragma unroll
            for (int t=0;t<4;t++) acc[i][j][t] = 0.f;

    for (int k0 = 0; k0 < K; k0 += 32){
        // stage A hi/lo: BM rows x 32 k (4 uint4 per row)
#pragma unroll
        for (int i = tid; i < BM*4; i += 256){
            int r = i >> 2, c = i & 3;
            long gofs = (long)(m0+r)*lda + k0 + c*8;
            *(uint4*)&sAh[r*KS + c*8] = *(const uint4*)(Ah + gofs);
            *(uint4*)&sAl[r*KS + c*8] = *(const uint4*)(Al + gofs);
        }
#pragma unroll
        for (int i = tid; i < BN*4; i += 256){
            int r = i >> 2, c = i & 3;
            long gofs = (long)(n0+r)*ldb + k0 + c*8;
            *(uint4*)&sBh[r*KS + c*8] = *(const uint4*)(Bh + gofs);
            *(uint4*)&sBl[r*KS + c*8] = *(const uint4*)(Bl + gofs);
        }
        __syncthreads();

#pragma unroll
        for (int ks = 0; ks < 32; ks += 16){
            const int kr = ks + tg*2;
            uint32_t ah[MF][4], al[MF][4], bh[NF][2], bl[NF][2];
#pragma unroll
            for (int mf = 0; mf < MF; mf++){
                int ar = wm*WTM + mf*16 + g;
                ah[mf][0] = *(const uint32_t*)&sAh[ ar   *KS + kr    ];
                ah[mf][1] = *(const uint32_t*)&sAh[(ar+8)*KS + kr    ];
                ah[mf][2] = *(const uint32_t*)&sAh[ ar   *KS + kr + 8];
                ah[mf][3] = *(const uint32_t*)&sAh[(ar+8)*KS + kr + 8];
                al[mf][0] = *(const uint32_t*)&sAl[ ar   *KS + kr    ];
                al[mf][1] = *(const uint32_t*)&sAl[(ar+8)*KS + kr    ];
                al[mf][2] = *(const uint32_t*)&sAl[ ar   *KS + kr + 8];
                al[mf][3] = *(const uint32_t*)&sAl[(ar+8)*KS + kr + 8];
            }
#pragma unroll
            for (int nf = 0; nf < NF; nf++){
                int br = wn*WTN + nf*8 + g;
                bh[nf][0] = *(const uint32_t*)&sBh[br*KS + kr    ];
                bh[nf][1] = *(const uint32_t*)&sBh[br*KS + kr + 8];
                bl[nf][0] = *(const uint32_t*)&sBl[br*KS + kr    ];
                bl[nf][1] = *(const uint32_t*)&sBl[br*KS + kr + 8];
            }
#pragma unroll
            for (int mf = 0; mf < MF; mf++)
#pragma unroll
                for (int nf = 0; nf < NF; nf++){
                    MMA_BF16(acc[mf][nf], ah[mf], bh[nf]);
                    MMA_BF16(acc[mf][nf], ah[mf], bl[nf]);
                    MMA_BF16(acc[mf][nf], al[mf], bh[nf]);
                }
        }
        __syncthreads();
    }

    // epilogue
#pragma unroll
    for (int mf = 0; mf < MF; mf++){
#pragma unroll
        for (int half = 0; half < 2; half++){
            long row = m0 + wm*WTM + mf*16 + g + half*8;
#pragma unroll
            for (int nf = 0; nf < NF; nf++){
                int col = n0 + wn*WTN + nf*8 + tg*2;
                float v0 = acc[mf][nf][half*2+0];
                float v1 = acc[mf][nf][half*2+1];
                if (EPI == 2){
                    v0 = tanhf(v0 + bias[col]);
                    v1 = tanhf(v1 + bias[col+1]);
                }
                long base = co + row*ldc + col;
                *(float2*)(C + base) = make_float2(v0, v1);
                if (EPI == 1){
                    split_write(v0, Ch, Cl, base);
                    split_write(v1, Ch, Cl, base+1);
                }
            }
        }
    }
}

// ---------------- softmax of raw scores -> bf16 hi/lo P ----------------
__global__ void softmax_split(const float* __restrict__ S,
                              __nv_bfloat16* __restrict__ Ph, __nv_bfloat16* __restrict__ Pl){
    __shared__ float sh[33];
    const float* row = S + (long)blockIdx.y*SEQ*SEQ + (long)blockIdx.x*SEQ;
    long obase = (long)blockIdx.y*SEQ*SEQ + (long)blockIdx.x*SEQ;
    float m = -1e30f;
    for (int d=threadIdx.x; d<SEQ; d+=blockDim.x) m = fmaxf(m, row[d]);
    m = block_red_max(m, sh);
    float sum = 0.f;
    for (int d=threadIdx.x; d<SEQ; d+=blockDim.x) sum += __expf((row[d]-m)*SCALE);
    sum = block_red_sum(sum, sh);
    float inv = 1.0f/sum;
    for (int d=threadIdx.x; d<SEQ; d+=blockDim.x){
        float p = __expf((row[d]-m)*SCALE) * inv;
        split_write(p, Ph, Pl, obase + d);
    }
}

// ---------------- V transpose (global heads) -> Vt[z][n(64)][k(2048)] --------
__global__ void vtrans(const float* __restrict__ v,
                       __nv_bfloat16* __restrict__ vth, __nv_bfloat16* __restrict__ vtl){
    __shared__ float t[32][33];
    int z = blockIdx.z, b = z>>1, h = z&1;
    int k0 = blockIdx.x*32, n0 = blockIdx.y*32;
    for (int i = threadIdx.y; i < 32; i += 8)
        t[i][threadIdx.x] = v[(long)(b*SEQ + k0 + i)*DM + h*HD + n0 + threadIdx.x];
    __syncthreads();
    for (int i = threadIdx.y; i < 32; i += 8){
        float val = t[threadIdx.x][i];
        long o = (long)z*HD*SEQ + (long)(n0+i)*SEQ + k0 + threadIdx.x;
        split_write(val, vth, vtl, o);
    }
}

// ---------------- sparse heads: one warp per query ----------------
__global__ void sparse_attn(const float* __restrict__ Q, const float* __restrict__ Kk,
                            const float* __restrict__ V, float* __restrict__ O){
    int hy = blockIdx.y;            // 0..5 -> heads 2..7
    int h  = hy + 2;
    int b  = blockIdx.z;
    int wid = threadIdx.x >> 5, lane = threadIdx.x & 31;
    int q = blockIdx.x*4 + wid;

    int w   = (hy==1) ? 128 : (hy==2) ? 256 : 64;
    int dil = (hy<3)  ? 1   : (1 << (hy-2));

    __shared__ float qs[4][64];
    __shared__ float pbuf[4][520];

    const float* qrow = Q + ((long)(b*SEQ + q)*DM + h*HD);
    qs[wid][lane]    = qrow[lane];
    qs[wid][lane+32] = qrow[lane+32];
    __syncwarp();

    int jlo = -min(w, q/dil);
    int jhi =  min(w, (SEQ-1-q)/dil);
    int cnt = jhi - jlo + 1;

    const float* Kbase = Kk + ((long)b*SEQ*DM + h*HD);
    const float* Vbase = V  + ((long)b*SEQ*DM + h*HD);

    float mmax = -1e30f;
    for (int jj=lane; jj<cnt; jj+=32){
        int k = q + (jlo+jj)*dil;
        const float* kr = Kbase + (long)k*DM;
        float s = 0.f;
#pragma unroll
        for (int d=0; d<HD; d+=4){
            float4 kv = *(const float4*)(kr+d);
            s += qs[wid][d]*kv.x + qs[wid][d+1]*kv.y + qs[wid][d+2]*kv.z + qs[wid][d+3]*kv.w;
        }
        s *= SCALE;
        pbuf[wid][jj] = s;
        mmax = fmaxf(mmax, s);
    }
    mmax = warp_red_max(mmax);
    float sum = 0.f;
    for (int jj=lane; jj<cnt; jj+=32){
        float e = __expf(pbuf[wid][jj] - mmax);
        pbuf[wid][jj] = e;
        sum += e;
    }
    sum = warp_red_sum(sum);
    float inv = 1.0f/sum;
    __syncwarp();

    float o0=0.f, o1=0.f;
    for (int jj=0; jj<cnt; jj++){
        int k = q + (jlo+jj)*dil;
        float p = pbuf[wid][jj];
        const float* vr = Vbase + (long)k*DM;
        o0 += p*vr[lane];
        o1 += p*vr[lane+32];
    }
    float* orow = O + ((long)(b*SEQ + q)*DM + h*HD);
    orow[lane]    = o0*inv;
    orow[lane+32] = o1*inv;
}

// ---------------- T gate ----------------
__global__ void tdot_kernel(const float* __restrict__ t1, const float* __restrict__ w2,
                            const float* __restrict__ b2, float* __restrict__ tl){
    __shared__ float sh[33];
    int row = blockIdx.x;
    const float* tr = t1 + (long)row*DM;
    float s = 0.f;
    for (int d=threadIdx.x; d<DM; d+=blockDim.x) s += tr[d]*w2[d];
    s = block_red_sum(s, sh);
    if (threadIdx.x==0) tl[row] = s + b2[0];
}
__global__ void tsoftmax_kernel(float* __restrict__ tl){
    __shared__ float sh[33];
    float* p = tl + (long)blockIdx.x*SEQ;
    int tid = threadIdx.x;
    float v0 = p[tid], v1 = p[tid+1024];
    float m = block_red_max(fmaxf(v0,v1), sh);
    float e0 = __expf(v0-m), e1 = __expf(v1-m);
    float s = block_red_sum(e0+e1, sh);
    float inv = 1.0f/s;
    p[tid] = e0*inv; p[tid+1024] = e1*inv;
}

// ---------------- final ----------------
__global__ void final_kernel(const float* __restrict__ proj, const float* __restrict__ x0,
                             const float* __restrict__ tl, const float* __restrict__ g,
                             const float* __restrict__ b, float* __restrict__ out){
    __shared__ float sh[33];
    int row = blockIdx.x;
    float t = tl[row];
    const float* pr = proj + (long)row*DM;
    const float* xr = x0   + (long)row*DM;
    float s=0.f, s2=0.f;
    for (int d=threadIdx.x; d<DM; d+=blockDim.x){
        float v = pr[d]*t + xr[d];
        s += v; s2 += v*v;
    }
    s  = block_red_sum(s,  sh);
    s2 = block_red_sum(s2, sh);
    float mu  = s * (1.0f/DM);
    float var = s2 * (1.0f/DM) - mu*mu;
    float inv = rsqrtf(var + EPS);
    float* o = out + (long)row*DM;
    for (int d=threadIdx.x; d<DM; d+=blockDim.x){
        float v = pr[d]*t + xr[d];
        o[d] = (v-mu)*inv*g[d] + b[d];
    }
}

// ---------------- launcher ----------------
extern "C" void kernel_launch(void* const* d_in, const int* in_sizes, int n_in,
                              void* d_out, int out_size)
{
    const float* x      = (const float*)d_in[0];
    const float* Wq     = (const float*)d_in[1];
    const float* Wk     = (const float*)d_in[2];
    const float* Wv     = (const float*)d_in[3];
    const float* Wo     = (const float*)d_in[4];
    const float* T_w1   = (const float*)d_in[5];
    const float* T_b1   = (const float*)d_in[6];
    const float* T_w2   = (const float*)d_in[7];
    const float* T_b2   = (const float*)d_in[8];
    const float* ln_in_g  = (const float*)d_in[9];
    const float* ln_in_b  = (const float*)d_in[10];
    const float* ln_out_g = (const float*)d_in[11];
    const float* ln_out_b = (const float*)d_in[12];
    float* out = (float*)d_out;

    float *q,*k,*v,*t1,*attn,*proj,*s,*tl;
    __nv_bfloat16 *xnh,*xnl,*qh,*ql,*kh,*kl,*ah,*al;
    __nv_bfloat16 *wqh,*wql,*wkh,*wkl,*wvh,*wvl,*woh,*wol,*w1h,*w1l;
    __nv_bfloat16 *ph,*pl,*vth,*vtl;
    cudaGetSymbolAddress((void**)&q,    g_q);
    cudaGetSymbolAddress((void**)&k,    g_k);
    cudaGetSymbolAddress((void**)&v,    g_v);
    cudaGetSymbolAddress((void**)&t1,   g_t1);
    cudaGetSymbolAddress((void**)&attn, g_attn);
    cudaGetSymbolAddress((void**)&proj, g_proj);
    cudaGetSymbolAddress((void**)&s,    g_s);
    cudaGetSymbolAddress((void**)&tl,   g_tl);
    cudaGetSymbolAddress((void**)&xnh,  g_xnh);  cudaGetSymbolAddress((void**)&xnl, g_xnl);
    cudaGetSymbolAddress((void**)&qh,   g_qh);   cudaGetSymbolAddress((void**)&ql,  g_ql);
    cudaGetSymbolAddress((void**)&kh,   g_kh);   cudaGetSymbolAddress((void**)&kl,  g_kl);
    cudaGetSymbolAddress((void**)&ah,   g_ah);   cudaGetSymbolAddress((void**)&al,  g_al);
    cudaGetSymbolAddress((void**)&wqh,  g_wqh);  cudaGetSymbolAddress((void**)&wql, g_wql);
    cudaGetSymbolAddress((void**)&wkh,  g_wkh);  cudaGetSymbolAddress((void**)&wkl, g_wkl);
    cudaGetSymbolAddress((void**)&wvh,  g_wvh);  cudaGetSymbolAddress((void**)&wvl, g_wvl);
    cudaGetSymbolAddress((void**)&woh,  g_woh);  cudaGetSymbolAddress((void**)&wol, g_wol);
    cudaGetSymbolAddress((void**)&w1h,  g_w1h);  cudaGetSymbolAddress((void**)&w1l, g_w1l);
    cudaGetSymbolAddress((void**)&ph,   g_ph);   cudaGetSymbolAddress((void**)&pl,  g_pl);
    cudaGetSymbolAddress((void**)&vth,  g_vth);  cudaGetSymbolAddress((void**)&vtl, g_vtl);

    // 1. input LN -> bf16 split
    ln_split<<<ROWS,128>>>(x, ln_in_g, ln_in_b, xnh, xnl);
    // 2. weight splits
    split2<<<256,256>>>(Wq,   wqh, wql, (long)DM*DM);
    split2<<<256,256>>>(Wk,   wkh, wkl, (long)DM*DM);
    split2<<<256,256>>>(Wv,   wvh, wvl, (long)DM*DM);
    split2<<<256,256>>>(Wo,   woh, wol, (long)DM*DM);
    split2<<<256,256>>>(T_w1, w1h, w1l, (long)DM*DM);

    // 3. projections (128x128 tiles, 8 warps 4x2)
    dim3 gp(DM/128, ROWS/128, 1);
    hmma_gemm<128,128,4,2,1><<<gp,256>>>(xnh,xnl, wqh,wql, q,  qh, ql, nullptr,
                                         DM, DM,DM,DM, 0,0,0,0,0,0);
    hmma_gemm<128,128,4,2,1><<<gp,256>>>(xnh,xnl, wkh,wkl, k,  kh, kl, nullptr,
                                         DM, DM,DM,DM, 0,0,0,0,0,0);
    hmma_gemm<128,128,4,2,0><<<gp,256>>>(xnh,xnl, wvh,wvl, v,  nullptr,nullptr, nullptr,
                                         DM, DM,DM,DM, 0,0,0,0,0,0);
    hmma_gemm<128,128,4,2,2><<<gp,256>>>(xnh,xnl, w1h,w1l, t1, nullptr,nullptr, T_b1,
                                         DM, DM,DM,DM, 0,0,0,0,0,0);

    // 4. T gate
    tdot_kernel<<<ROWS,128>>>(t1, T_w2, T_b2, tl);
    tsoftmax_kernel<<<BATCH,1024>>>(tl);

    // 5. global heads: S = Q K^T ; softmax ; P V
    {
        dim3 gqk(SEQ/128, SEQ/128, 4);
        hmma_gemm<128,128,4,2,0><<<gqk,256>>>(qh,ql, kh,kl, s, nullptr,nullptr, nullptr,
                                              HD, DM, DM, SEQ,
                                              (long)SEQ*DM, HD, (long)SEQ*DM, HD,
                                              2L*SEQ*SEQ, (long)SEQ*SEQ);
        softmax_split<<<dim3(SEQ,4),256>>>(s, ph, pl);
        vtrans<<<dim3(SEQ/32, HD/32, 4), dim3(32,8)>>>(v, vth, vtl);
        dim3 gpv(1, SEQ/64, 4);
        hmma_gemm<64,64,2,4,0><<<gpv,256>>>(ph,pl, vth,vtl, attn, nullptr,nullptr, nullptr,
                                            SEQ, SEQ, SEQ, DM,
                                            2L*SEQ*SEQ, (long)SEQ*SEQ,
                                            2L*HD*SEQ, (long)HD*SEQ,
                                            (long)SEQ*DM, HD);
    }

    // 6. sparse heads (h=2..7)
    sparse_attn<<<dim3(SEQ/4,6,BATCH),128>>>(q, k, v, attn);

    // 7. output projection
    split2<<<512,256>>>(attn, ah, al, (long)ROWS*DM);
    hmma_gemm<128,128,4,2,0><<<gp,256>>>(ah,al, woh,wol, proj, nullptr,nullptr, nullptr,
                                         DM, DM,DM,DM, 0,0,0,0,0,0);

    // 8. gate * out + residual + output LN
    final_kernel<<<ROWS,128>>>(proj, x, tl, ln_out_g, ln_out_b, out);
}